// round 13
// baseline (speedup 1.0000x reference)
#include <cuda_runtime.h>

// MultiKR fused forward on GB300 (sm_103a), v5: tf32x3 tensor GEMMs,
// 512 threads / 16 warps with N-split (warp = 16 rows x 64 cols).
//  - mma.sync.aligned.m16n8k8 tf32, fp32 accumulate, 3-term split (fp32-grade)
//  - weights pre-split/pre-packed in fragment order by converter kernel
//  - activations fp32 in smem (stride 132 -> conflict-free fragment loads)
//  - cp.async double-buffered 8-row weight k-tiles
//
// Inputs (metadata order):
//  0 user_ids int32[16384]  1 item_ids int32[16384]  2 rec_target f32[16384]
//  3 user_tbl f32[100000,128] 4 item_tbl f32[50000,128] 5 entity_tbl f32[50000,128]
//  6-9 w_vv/w_ev/w_ve/w_ee f32[128]  10 bias_v 11 bias_e
// 12 Wu f32[128,128] 13 bu  14 W1 f32[256,256] 15 b1
// 16 W2 f32[256,128] 17 b2  18 W3 f32[128,1]   19 b3
// output: concat(rec_out[16384], rec_target[16384]) f32

#define B_TOT    16384
#define D        128
#define H1       256
#define H2       128
#define TM       128          // rows per CTA
#define NTHREADS 512
#define AST      132          // activation smem row stride (floats)

// dynamic smem (float offsets)
//  Us   [     0, 16896)
//  Is   [ 16896, 33792)
//  Hs   [ 33792, 50688)
//  Ws   [ 50688, 54784)   two k-tile buffers x 2048 floats (hi 1024 | lo 1024)
//  vw   [ 54784, 55296)
//  dots [ 55296, 55808)
#define SM_FLOATS 55808

// ---- fragment-packed split weights (written by converter kernel each launch)
// per k-step tile t (8 k-rows): 2048 floats = [hi: j(16) x lane(32) x p(2)][lo: same]
__device__ float g_cWu[16 * 2048];
__device__ float g_cW1[2 * 32 * 2048];
__device__ float g_cW2[32 * 2048];

__device__ __forceinline__ unsigned tf32u(float x) {
    unsigned u;
    asm("cvt.rna.tf32.f32 %0, %1;" : "=r"(u) : "f"(x));
    return u;
}
__device__ __forceinline__ float tf32f(float x) { return __uint_as_float(tf32u(x)); }

__global__ void convert_weights_kernel(const float* __restrict__ Wu,
                                       const float* __restrict__ W1,
                                       const float* __restrict__ W2)
{
    int i = blockIdx.x * blockDim.x + threadIdx.x;
    if (i >= 16384 + 65536 + 32768) return;
    float w; float* base; int k, n;
    if (i < 16384)      { k = i >> 7;  n = i & 127;  w = Wu[i]; base = g_cWu; }
    else if (i < 81920) { int s = i - 16384; k = s >> 8; int nf = s & 255;
                          w = W1[s]; base = g_cW1 + (nf >> 7) * (32 * 2048); n = nf & 127; }
    else                { int s = i - 81920; k = s >> 7; n = s & 127; w = W2[s]; base = g_cW2; }
    // fragment mapping for mma.m16n8k8 .col B: b0 k=lane%4, b1 k=lane%4+4, n=lane/4
    int t = k >> 3, p = (k >> 2) & 1, km = k & 3;
    int j = n >> 3, l = (n & 7) * 4 + km;
    int off = t * 2048 + j * 64 + l * 2 + p;
    float hi = tf32f(w);
    float lo = tf32f(w - hi);
    base[off]        = hi;
    base[off + 1024] = lo;
}

// ---- cp.async helpers ----
__device__ __forceinline__ void cp16(float* dst, const float* src) {
    unsigned s = (unsigned)__cvta_generic_to_shared(dst);
    asm volatile("cp.async.cg.shared.global [%0], [%1], 16;\n" :: "r"(s), "l"(src));
}
#define CP_COMMIT() asm volatile("cp.async.commit_group;\n" ::: "memory")
#define CP_WAIT0()  asm volatile("cp.async.wait_group 0;\n" ::: "memory")

// stage one 2048-float packed tile (512 threads x 1 cp16)
__device__ __forceinline__ void stage8(float* dst, const float* src, int tid) {
    cp16(dst + tid * 4, src + tid * 4);
}

__device__ __forceinline__ void mma8(float acc[4],
                                     unsigned a0, unsigned a1, unsigned a2, unsigned a3,
                                     unsigned b0, unsigned b1)
{
    asm("mma.sync.aligned.m16n8k8.row.col.f32.tf32.tf32.f32 "
        "{%0,%1,%2,%3},{%4,%5,%6,%7},{%8,%9},{%0,%1,%2,%3};"
        : "+f"(acc[0]), "+f"(acc[1]), "+f"(acc[2]), "+f"(acc[3])
        : "r"(a0), "r"(a1), "r"(a2), "r"(a3), "r"(b0), "r"(b1));
}

// GEMM: C[TM x 128] += A * W ; A = [A0 | A1] switching at tswitch.
// Warp covers 16 rows x 64 cols (8 n-tiles at jbase). 3-term tf32 split.
__device__ __forceinline__ void gemm_tf32(const float* __restrict__ A0,
                                          const float* __restrict__ A1, int tswitch,
                                          const float* __restrict__ Wsrc, int ksteps,
                                          float* Ws, int tid, int lane, int r0, int jbase,
                                          float acc[8][4], bool prefetched)
{
    if (!prefetched) { stage8(Ws, Wsrc, tid); CP_COMMIT(); }
    for (int t = 0; t < ksteps; ++t) {
        CP_WAIT0(); __syncthreads();
        if (t + 1 < ksteps) { stage8(Ws + ((t + 1) & 1) * 2048, Wsrc + (t + 1) * 2048, tid); CP_COMMIT(); }
        const float* A = (t < tswitch) ? A0 : A1;
        const int kk = (t * 8) & 127;
        const int ra = (r0 + (lane >> 2)) * AST + kk + (lane & 3);
        float a0f = A[ra];
        float a1f = A[ra + 8 * AST];
        float a2f = A[ra + 4];
        float a3f = A[ra + 8 * AST + 4];
        unsigned ah0 = tf32u(a0f), ah1 = tf32u(a1f), ah2 = tf32u(a2f), ah3 = tf32u(a3f);
        unsigned al0 = tf32u(a0f - __uint_as_float(ah0));
        unsigned al1 = tf32u(a1f - __uint_as_float(ah1));
        unsigned al2 = tf32u(a2f - __uint_as_float(ah2));
        unsigned al3 = tf32u(a3f - __uint_as_float(ah3));
        const float* Wb = Ws + (t & 1) * 2048;
        #pragma unroll
        for (int j = 0; j < 8; ++j) {
            const int jj = jbase + j;
            float2 bh = *(const float2*)(Wb + jj * 64 + lane * 2);
            float2 bl = *(const float2*)(Wb + 1024 + jj * 64 + lane * 2);
            unsigned bh0 = __float_as_uint(bh.x), bh1 = __float_as_uint(bh.y);
            unsigned bl0 = __float_as_uint(bl.x), bl1 = __float_as_uint(bl.y);
            mma8(acc[j], ah0, ah1, ah2, ah3, bh0, bh1);
            mma8(acc[j], al0, al1, al2, al3, bh0, bh1);
            mma8(acc[j], ah0, ah1, ah2, ah3, bl0, bl1);
        }
    }
}

__device__ __forceinline__ void acc_clear(float acc[8][4]) {
    #pragma unroll
    for (int j = 0; j < 8; ++j)
        #pragma unroll
        for (int c = 0; c < 4; ++c) acc[j][c] = 0.f;
}

// relu(acc + bias) -> Dst (stride AST); warp covers cols [jbase*8, jbase*8+64)
__device__ __forceinline__ void epilogue(float acc[8][4], float* Dst,
                                         const float* bias, int lane, int r0, int jbase)
{
    const int row = r0 + (lane >> 2);
    const int cb  = 2 * (lane & 3);
    #pragma unroll
    for (int j = 0; j < 8; ++j) {
        int col = 8 * (jbase + j) + cb;
        float2 v0, v1;
        v0.x = fmaxf(acc[j][0] + bias[col],     0.f);
        v0.y = fmaxf(acc[j][1] + bias[col + 1], 0.f);
        v1.x = fmaxf(acc[j][2] + bias[col],     0.f);
        v1.y = fmaxf(acc[j][3] + bias[col + 1], 0.f);
        *(float2*)(Dst + row * AST + col)       = v0;
        *(float2*)(Dst + (row + 8) * AST + col) = v1;
    }
}

__global__ __launch_bounds__(NTHREADS, 1)
void multikr_kernel(const int*   __restrict__ user_ids,
                    const int*   __restrict__ item_ids,
                    const float* __restrict__ rec_target,
                    const float* __restrict__ user_tbl,
                    const float* __restrict__ item_tbl,
                    const float* __restrict__ entity_tbl,
                    const float* __restrict__ w_vv,
                    const float* __restrict__ w_ev,
                    const float* __restrict__ w_ve,
                    const float* __restrict__ w_ee,
                    const float* __restrict__ bias_v_p,
                    const float* __restrict__ bias_e_p,
                    const float* __restrict__ bu,
                    const float* __restrict__ b1,
                    const float* __restrict__ b2,
                    const float* __restrict__ W3,
                    const float* __restrict__ b3,
                    float* __restrict__ out,
                    int out_size)
{
    extern __shared__ float sm[];
    float* Us   = sm;
    float* Is   = sm + 16896;
    float* Hs   = sm + 33792;
    float* Ws   = sm + 50688;
    float* vw   = sm + 54784;
    float* dots = sm + 55296;

    __shared__ int   s_uid[TM];
    __shared__ int   s_iid[TM];
    __shared__ float s_bu[D];
    __shared__ float s_b1[H1];
    __shared__ float s_b2[H2];
    __shared__ float s_w3[H2];

    const int tid   = threadIdx.x;
    const int lane  = tid & 31;
    const int wid   = tid >> 5;          // 0..15
    const int r0    = (wid >> 1) * 16;   // 8 row-groups of 16
    const int jbase = (wid & 1) * 8;     // n-half: tiles [jbase, jbase+8)
    const int b0    = blockIdx.x * TM;

    if (tid < TM) {
        s_uid[tid] = user_ids[b0 + tid];
        s_iid[tid] = item_ids[b0 + tid];
        vw[tid]       = w_vv[tid];
        vw[128 + tid] = w_ev[tid];
        vw[256 + tid] = w_ve[tid];
        vw[384 + tid] = w_ee[tid];
        s_bu[tid] = bu[tid];
        s_b2[tid] = b2[tid];
        s_w3[tid] = W3[tid];
    }
    if (tid < H1) s_b1[tid] = b1[tid];

    // prefetch first Wu tile (Ws disjoint; overlaps with the gather)
    stage8(Ws, g_cWu, tid); CP_COMMIT();
    __syncthreads();

    // ---- gather embedding rows (coalesced float4, stride AST) ----
    {
        const float4* ut = (const float4*)user_tbl;
        const float4* it = (const float4*)item_tbl;
        const float4* et = (const float4*)entity_tbl;
        float4* U4 = (float4*)Us;
        float4* I4 = (float4*)Is;
        float4* H4 = (float4*)Hs;
        #pragma unroll
        for (int t = 0; t < (TM * 32) / NTHREADS; ++t) {
            int idx = tid + t * NTHREADS;
            int row = idx >> 5, q = idx & 31;
            U4[row * (AST / 4) + q] = ut[(long)s_uid[row] * 32 + q];
            I4[row * (AST / 4) + q] = it[(long)s_iid[row] * 32 + q];
            H4[row * (AST / 4) + q] = et[(long)s_iid[row] * 32 + q];
        }
    }
    __syncthreads();

    const float bias_v = bias_v_p[0];
    const float bias_e = bias_e_p[0];

    float acc[8][4];

    // =========================== layer loop ===========================
    for (int layer = 0; layer < 2; ++layer) {
        // ---- user = relu(user @ Wu + bu) ----
        acc_clear(acc);
        gemm_tf32(Us, Us, 16, g_cWu, 16, Ws, tid, lane, r0, jbase, acc, layer == 0);
        __syncthreads();                 // all reads of Us done
        epilogue(acc, Us, s_bu, lane, r0, jbase);
        __syncthreads();

        // ---- cross-compress ----
        if (tid < TM) {
            const int row = tid;
            const float* ir = Is + row * AST;
            const float* hr = Hs + row * AST;
            float hv = 0.f, iv = 0.f, he = 0.f, ie = 0.f;
            #pragma unroll 4
            for (int kk = 0; kk < D; ++kk) {
                int k = (kk + row) & (D - 1);
                float iva = ir[k], hva = hr[k];
                hv = fmaf(hva, vw[k],       hv);
                iv = fmaf(iva, vw[128 + k], iv);
                he = fmaf(hva, vw[256 + k], he);
                ie = fmaf(iva, vw[384 + k], ie);
            }
            dots[row]       = hv;
            dots[128 + row] = iv;
            dots[256 + row] = he;
            dots[384 + row] = ie;
        }
        __syncthreads();
        #pragma unroll
        for (int t = 0; t < (TM * D) / NTHREADS; ++t) {
            int idx = tid + t * NTHREADS;
            int row = idx >> 7, col = idx & 127;
            int a = row * AST + col;
            float i0 = Is[a], h0 = Hs[a];
            float hv = dots[row],       iv = dots[128 + row];
            float he = dots[256 + row], ie = dots[384 + row];
            Is[a] = fmaf(i0, hv, fmaf(h0, iv, bias_v));
            Hs[a] = fmaf(i0, he, fmaf(h0, ie, bias_e));
        }
        __syncthreads();
    }

    // ================= MLP =================
    // h1 half0 -> Hs (head acts dead), half1 -> Us (user acts dead after reads)
    acc_clear(acc);
    gemm_tf32(Us, Is, 16, g_cW1, 32, Ws, tid, lane, r0, jbase, acc, false);
    __syncthreads();
    epilogue(acc, Hs, s_b1, lane, r0, jbase);
    __syncthreads();

    acc_clear(acc);
    gemm_tf32(Us, Is, 16, g_cW1 + 32 * 2048, 32, Ws, tid, lane, r0, jbase, acc, false);
    __syncthreads();
    epilogue(acc, Us, s_b1 + 128, lane, r0, jbase);
    __syncthreads();

    // h2 = relu([Hs|Us] @ W2 + b2) -> Is (item acts dead)
    acc_clear(acc);
    gemm_tf32(Hs, Us, 16, g_cW2, 32, Ws, tid, lane, r0, jbase, acc, false);
    __syncthreads();
    epilogue(acc, Is, s_b2, lane, r0, jbase);
    __syncthreads();

    // out = relu(h2 @ W3 + b3)
    if (tid < TM) {
        const int row = tid;
        const float* hr = Is + row * AST;
        float d = 0.f;
        #pragma unroll 4
        for (int kk = 0; kk < D; ++kk) {
            int k = (kk + row) & (D - 1);
            d = fmaf(hr[k], s_w3[k], d);
        }
        out[b0 + row] = fmaxf(d + b3[0], 0.f);
        if (out_size >= 2 * B_TOT)
            out[B_TOT + b0 + row] = rec_target[b0 + row];
    }
}

extern "C" void kernel_launch(void* const* d_in, const int* in_sizes, int n_in,
                              void* d_out, int out_size)
{
    (void)n_in; (void)in_sizes;
    const int*   user_ids   = (const int*)  d_in[0];
    const int*   item_ids   = (const int*)  d_in[1];
    const float* rec_target = (const float*)d_in[2];
    const float* user_tbl   = (const float*)d_in[3];
    const float* item_tbl   = (const float*)d_in[4];
    const float* entity_tbl = (const float*)d_in[5];
    const float* w_vv   = (const float*)d_in[6];
    const float* w_ev   = (const float*)d_in[7];
    const float* w_ve   = (const float*)d_in[8];
    const float* w_ee   = (const float*)d_in[9];
    const float* bias_v = (const float*)d_in[10];
    const float* bias_e = (const float*)d_in[11];
    const float* Wu = (const float*)d_in[12];
    const float* bu = (const float*)d_in[13];
    const float* W1 = (const float*)d_in[14];
    const float* b1 = (const float*)d_in[15];
    const float* W2 = (const float*)d_in[16];
    const float* b2 = (const float*)d_in[17];
    const float* W3 = (const float*)d_in[18];
    const float* b3 = (const float*)d_in[19];

    // 1) split + fragment-pack the weights (deterministic, graph-capturable)
    convert_weights_kernel<<<(16384 + 65536 + 32768 + 255) / 256, 256>>>(Wu, W1, W2);

    // 2) fused forward
    const size_t smem = SM_FLOATS * sizeof(float);   // ~218 KB
    cudaFuncSetAttribute(multikr_kernel,
                         cudaFuncAttributeMaxDynamicSharedMemorySize, (int)smem);
    multikr_kernel<<<B_TOT / TM, NTHREADS, smem>>>(
        user_ids, item_ids, rec_target, user_tbl, item_tbl, entity_tbl,
        w_vv, w_ev, w_ve, w_ee, bias_v, bias_e,
        bu, b1, b2, W3, b3,
        (float*)d_out, out_size);
}

// round 14
// speedup vs baseline: 1.4832x; 1.4832x over previous
#include <cuda_runtime.h>
#include <cuda_bf16.h>

// MultiKR fused forward on GB300 (sm_103a), v6: bf16x3 tensor GEMMs.
//  - mma.sync.aligned.m16n8k16.row.col.f32.bf16.bf16.f32, fp32 accumulate
//  - 3-term split (ah*bh + al*bh + ah*bl): per-product error ~2^-16 -> safe
//  - K=16 per mma (vs 8 for tf32): half the mma count, half the barriers
//  - weights pre-split/pre-packed in fragment order by converter kernel
//  - activations fp32 in smem (stride 132 -> conflict-free fragment loads)
//  - cp.async double-buffered 16-row weight k-tiles (8 KB, unchanged size)
//  - cross-compress parallelized across all 512 threads
//
// Inputs (metadata order):
//  0 user_ids int32[16384]  1 item_ids int32[16384]  2 rec_target f32[16384]
//  3 user_tbl f32[100000,128] 4 item_tbl f32[50000,128] 5 entity_tbl f32[50000,128]
//  6-9 w_vv/w_ev/w_ve/w_ee f32[128]  10 bias_v 11 bias_e
// 12 Wu f32[128,128] 13 bu  14 W1 f32[256,256] 15 b1
// 16 W2 f32[256,128] 17 b2  18 W3 f32[128,1]   19 b3
// output: concat(rec_out[16384], rec_target[16384]) f32

#define B_TOT    16384
#define D        128
#define H1       256
#define H2       128
#define TM       128          // rows per CTA
#define NTHREADS 512
#define AST      132          // activation smem row stride (floats)
#define VWS      136          // vw segment stride (conflict-free 4-type access)

// dynamic smem (float offsets)
//  Us   [     0, 16896)
//  Is   [ 16896, 33792)
//  Hs   [ 33792, 50688)
//  Ws   [ 50688, 54784)   two k16 tile buffers x 2048 words (hi 1024 | lo 1024)
//  vw   [ 54784, 55328)   4 segments x VWS
//  dots [ 55328, 55840)
#define SM_FLOATS 55840

// ---- fragment-packed split bf16 weights (written by converter each launch)
// per k16 tile t: 2048 32-bit words = [hi: j(16) x lane(32) x p(2)][lo: same]
// each word = bf16x2 (even k in low half, odd k in high half)
__device__ float g_cWu[8 * 2048];             // Wu: K=128 -> 8 tiles
__device__ float g_cW1[2 * 16 * 2048];        // W1 halves: K=256 -> 16 tiles each
__device__ float g_cW2[16 * 2048];            // W2: K=256 -> 16 tiles

__global__ void convert_weights_kernel(const float* __restrict__ Wu,
                                       const float* __restrict__ W1,
                                       const float* __restrict__ W2)
{
    int i = blockIdx.x * blockDim.x + threadIdx.x;
    if (i >= 16384 + 65536 + 32768) return;
    float w; float* base; int k, n;
    if (i < 16384)      { k = i >> 7;  n = i & 127;  w = Wu[i]; base = g_cWu; }
    else if (i < 81920) { int s = i - 16384; k = s >> 8; int nf = s & 255;
                          w = W1[s]; base = g_cW1 + (nf >> 7) * (16 * 2048); n = nf & 127; }
    else                { int s = i - 81920; k = s >> 7; n = s & 127; w = W2[s]; base = g_cW2; }
    // fragment mapping for mma.m16n8k16 .col B:
    //   b0: k = 2*(lane%4)+half (k 0..7), b1: k+8; n = lane/4 within 8-col tile
    int t = k >> 4, p = (k >> 3) & 1, h = k & 1;
    int j = n >> 3, l = (n & 7) * 4 + ((k & 7) >> 1);
    int off = t * 2048 + j * 64 + l * 2 + p;          // 32-bit word index (hi block)
    __nv_bfloat16 hi = __float2bfloat16_rn(w);
    __nv_bfloat16 lo = __float2bfloat16_rn(w - __bfloat162float(hi));
    __nv_bfloat16* bp = (__nv_bfloat16*)base;
    bp[off * 2 + h]            = hi;
    bp[(off + 1024) * 2 + h]   = lo;
}

// ---- cp.async helpers ----
__device__ __forceinline__ void cp16(float* dst, const float* src) {
    unsigned s = (unsigned)__cvta_generic_to_shared(dst);
    asm volatile("cp.async.cg.shared.global [%0], [%1], 16;\n" :: "r"(s), "l"(src));
}
#define CP_COMMIT() asm volatile("cp.async.commit_group;\n" ::: "memory")
#define CP_WAIT0()  asm volatile("cp.async.wait_group 0;\n" ::: "memory")

// stage one 2048-word packed tile (512 threads x 1 cp16)
__device__ __forceinline__ void stage8(float* dst, const float* src, int tid) {
    cp16(dst + tid * 4, src + tid * 4);
}

__device__ __forceinline__ unsigned packbf(float2 v) {
    __nv_bfloat162 h = __floats2bfloat162_rn(v.x, v.y);   // .x -> low half
    return *(unsigned*)&h;
}
__device__ __forceinline__ float2 resid(float2 v, unsigned hu) {
    __nv_bfloat162 hb = *(__nv_bfloat162*)&hu;
    float2 r;
    r.x = v.x - __bfloat162float(hb.x);
    r.y = v.y - __bfloat162float(hb.y);
    return r;
}

__device__ __forceinline__ void mma16(float acc[4],
                                      unsigned a0, unsigned a1, unsigned a2, unsigned a3,
                                      unsigned b0, unsigned b1)
{
    asm("mma.sync.aligned.m16n8k16.row.col.f32.bf16.bf16.f32 "
        "{%0,%1,%2,%3},{%4,%5,%6,%7},{%8,%9},{%0,%1,%2,%3};"
        : "+f"(acc[0]), "+f"(acc[1]), "+f"(acc[2]), "+f"(acc[3])
        : "r"(a0), "r"(a1), "r"(a2), "r"(a3), "r"(b0), "r"(b1));
}

// GEMM: C[TM x 128] += A * W ; A = [A0 | A1] switching at tswitch (k16 steps).
// Warp covers 16 rows x 64 cols (8 n-tiles at jbase). 3-term bf16 split.
__device__ __forceinline__ void gemm_bf16(const float* __restrict__ A0,
                                          const float* __restrict__ A1, int tswitch,
                                          const float* __restrict__ Wsrc, int ksteps,
                                          float* Ws, int tid, int lane, int r0, int jbase,
                                          float acc[8][4], bool prefetched)
{
    if (!prefetched) { stage8(Ws, Wsrc, tid); CP_COMMIT(); }
    for (int t = 0; t < ksteps; ++t) {
        CP_WAIT0(); __syncthreads();
        if (t + 1 < ksteps) { stage8(Ws + ((t + 1) & 1) * 2048, Wsrc + (t + 1) * 2048, tid); CP_COMMIT(); }
        const float* A = (t < tswitch) ? A0 : A1;
        const int kk = (t * 16) & 127;
        const int rr = r0 + (lane >> 2);
        const int cc = kk + 2 * (lane & 3);
        float2 v00 = *(const float2*)(A + rr * AST + cc);
        float2 v01 = *(const float2*)(A + rr * AST + cc + 8);
        float2 v10 = *(const float2*)(A + (rr + 8) * AST + cc);
        float2 v11 = *(const float2*)(A + (rr + 8) * AST + cc + 8);
        unsigned ah0 = packbf(v00), ah1 = packbf(v10), ah2 = packbf(v01), ah3 = packbf(v11);
        unsigned al0 = packbf(resid(v00, ah0));
        unsigned al1 = packbf(resid(v10, ah1));
        unsigned al2 = packbf(resid(v01, ah2));
        unsigned al3 = packbf(resid(v11, ah3));
        const float* Wb = Ws + (t & 1) * 2048;
        #pragma unroll
        for (int j = 0; j < 8; ++j) {
            const int jj = jbase + j;
            float2 bh = *(const float2*)(Wb + jj * 64 + lane * 2);
            float2 bl = *(const float2*)(Wb + 1024 + jj * 64 + lane * 2);
            unsigned bh0 = __float_as_uint(bh.x), bh1 = __float_as_uint(bh.y);
            unsigned bl0 = __float_as_uint(bl.x), bl1 = __float_as_uint(bl.y);
            mma16(acc[j], ah0, ah1, ah2, ah3, bh0, bh1);
            mma16(acc[j], al0, al1, al2, al3, bh0, bh1);
            mma16(acc[j], ah0, ah1, ah2, ah3, bl0, bl1);
        }
    }
}

__device__ __forceinline__ void acc_clear(float acc[8][4]) {
    #pragma unroll
    for (int j = 0; j < 8; ++j)
        #pragma unroll
        for (int c = 0; c < 4; ++c) acc[j][c] = 0.f;
}

// relu(acc + bias) -> Dst (stride AST); warp covers cols [jbase*8, jbase*8+64)
__device__ __forceinline__ void epilogue(float acc[8][4], float* Dst,
                                         const float* bias, int lane, int r0, int jbase)
{
    const int row = r0 + (lane >> 2);
    const int cb  = 2 * (lane & 3);
    #pragma unroll
    for (int j = 0; j < 8; ++j) {
        int col = 8 * (jbase + j) + cb;
        float2 v0, v1;
        v0.x = fmaxf(acc[j][0] + bias[col],     0.f);
        v0.y = fmaxf(acc[j][1] + bias[col + 1], 0.f);
        v1.x = fmaxf(acc[j][2] + bias[col],     0.f);
        v1.y = fmaxf(acc[j][3] + bias[col + 1], 0.f);
        *(float2*)(Dst + row * AST + col)       = v0;
        *(float2*)(Dst + (row + 8) * AST + col) = v1;
    }
}

__global__ __launch_bounds__(NTHREADS, 1)
void multikr_kernel(const int*   __restrict__ user_ids,
                    const int*   __restrict__ item_ids,
                    const float* __restrict__ rec_target,
                    const float* __restrict__ user_tbl,
                    const float* __restrict__ item_tbl,
                    const float* __restrict__ entity_tbl,
                    const float* __restrict__ w_vv,
                    const float* __restrict__ w_ev,
                    const float* __restrict__ w_ve,
                    const float* __restrict__ w_ee,
                    const float* __restrict__ bias_v_p,
                    const float* __restrict__ bias_e_p,
                    const float* __restrict__ bu,
                    const float* __restrict__ b1,
                    const float* __restrict__ b2,
                    const float* __restrict__ W3,
                    const float* __restrict__ b3,
                    float* __restrict__ out,
                    int out_size)
{
    extern __shared__ float sm[];
    float* Us   = sm;
    float* Is   = sm + 16896;
    float* Hs   = sm + 33792;
    float* Ws   = sm + 50688;
    float* vw   = sm + 54784;          // 4 segments of VWS
    float* dots = sm + 55328;

    __shared__ int   s_uid[TM];
    __shared__ int   s_iid[TM];
    __shared__ float s_bu[D];
    __shared__ float s_b1[H1];
    __shared__ float s_b2[H2];
    __shared__ float s_w3[H2];

    const int tid   = threadIdx.x;
    const int lane  = tid & 31;
    const int wid   = tid >> 5;          // 0..15
    const int r0    = (wid >> 1) * 16;   // 8 row-groups of 16
    const int jbase = (wid & 1) * 8;     // n-half: tiles [jbase, jbase+8)
    const int b0    = blockIdx.x * TM;

    if (tid < TM) {
        s_uid[tid] = user_ids[b0 + tid];
        s_iid[tid] = item_ids[b0 + tid];
        vw[tid]           = w_vv[tid];   // seg 0: head . w_vv -> hv
        vw[VWS + tid]     = w_ev[tid];   // seg 1: item . w_ev -> iv
        vw[2 * VWS + tid] = w_ve[tid];   // seg 2: head . w_ve -> he
        vw[3 * VWS + tid] = w_ee[tid];   // seg 3: item . w_ee -> ie
        s_bu[tid] = bu[tid];
        s_b2[tid] = b2[tid];
        s_w3[tid] = W3[tid];
    }
    if (tid < H1) s_b1[tid] = b1[tid];

    // prefetch first Wu tile (Ws disjoint; overlaps with the gather)
    stage8(Ws, g_cWu, tid); CP_COMMIT();
    __syncthreads();

    // ---- gather embedding rows (coalesced float4, stride AST) ----
    {
        const float4* ut = (const float4*)user_tbl;
        const float4* it = (const float4*)item_tbl;
        const float4* et = (const float4*)entity_tbl;
        float4* U4 = (float4*)Us;
        float4* I4 = (float4*)Is;
        float4* H4 = (float4*)Hs;
        #pragma unroll
        for (int t = 0; t < (TM * 32) / NTHREADS; ++t) {
            int idx = tid + t * NTHREADS;
            int row = idx >> 5, q = idx & 31;
            U4[row * (AST / 4) + q] = ut[(long)s_uid[row] * 32 + q];
            I4[row * (AST / 4) + q] = it[(long)s_iid[row] * 32 + q];
            H4[row * (AST / 4) + q] = et[(long)s_iid[row] * 32 + q];
        }
    }
    __syncthreads();

    const float bias_v = bias_v_p[0];
    const float bias_e = bias_e_p[0];

    float acc[8][4];

    // =========================== layer loop ===========================
    for (int layer = 0; layer < 2; ++layer) {
        // ---- user = relu(user @ Wu + bu) ----
        acc_clear(acc);
        gemm_bf16(Us, Us, 8, g_cWu, 8, Ws, tid, lane, r0, jbase, acc, layer == 0);
        __syncthreads();                 // all reads of Us done
        epilogue(acc, Us, s_bu, lane, r0, jbase);
        __syncthreads();

        // ---- cross-compress: one dot per thread (512 = 128 rows x 4 dots) ----
        {
            const int row  = tid >> 2;
            const int type = tid & 3;
            const float* src = (type & 1) ? Is : Hs;   // 0,2: head; 1,3: item
            const float* wv  = vw + type * VWS;
            const float* sr  = src + row * AST;
            float d = 0.f;
            #pragma unroll 4
            for (int kk = 0; kk < D; ++kk) {
                int k = (kk + row) & (D - 1);          // row-skewed
                d = fmaf(sr[k], wv[k], d);
            }
            dots[type * 128 + row] = d;
        }
        __syncthreads();
        #pragma unroll
        for (int t = 0; t < (TM * D) / NTHREADS; ++t) {
            int idx = tid + t * NTHREADS;
            int row = idx >> 7, col = idx & 127;
            int a = row * AST + col;
            float i0 = Is[a], h0 = Hs[a];
            float hv = dots[row],       iv = dots[128 + row];
            float he = dots[256 + row], ie = dots[384 + row];
            Is[a] = fmaf(i0, hv, fmaf(h0, iv, bias_v));
            Hs[a] = fmaf(i0, he, fmaf(h0, ie, bias_e));
        }
        __syncthreads();
    }

    // ================= MLP =================
    // h1 half0 -> Hs (head acts dead), half1 -> Us (user acts dead after reads)
    acc_clear(acc);
    gemm_bf16(Us, Is, 8, g_cW1, 16, Ws, tid, lane, r0, jbase, acc, false);
    __syncthreads();
    epilogue(acc, Hs, s_b1, lane, r0, jbase);
    __syncthreads();

    acc_clear(acc);
    gemm_bf16(Us, Is, 8, g_cW1 + 16 * 2048, 16, Ws, tid, lane, r0, jbase, acc, false);
    __syncthreads();
    epilogue(acc, Us, s_b1 + 128, lane, r0, jbase);
    __syncthreads();

    // h2 = relu([Hs|Us] @ W2 + b2) -> Is (item acts dead)
    acc_clear(acc);
    gemm_bf16(Hs, Us, 8, g_cW2, 16, Ws, tid, lane, r0, jbase, acc, false);
    __syncthreads();
    epilogue(acc, Is, s_b2, lane, r0, jbase);
    __syncthreads();

    // out = relu(h2 @ W3 + b3)
    if (tid < TM) {
        const int row = tid;
        const float* hr = Is + row * AST;
        float d = 0.f;
        #pragma unroll 4
        for (int kk = 0; kk < D; ++kk) {
            int k = (kk + row) & (D - 1);
            d = fmaf(hr[k], s_w3[k], d);
        }
        out[b0 + row] = fmaxf(d + b3[0], 0.f);
        if (out_size >= 2 * B_TOT)
            out[B_TOT + b0 + row] = rec_target[b0 + row];
    }
}

extern "C" void kernel_launch(void* const* d_in, const int* in_sizes, int n_in,
                              void* d_out, int out_size)
{
    (void)n_in; (void)in_sizes;
    const int*   user_ids   = (const int*)  d_in[0];
    const int*   item_ids   = (const int*)  d_in[1];
    const float* rec_target = (const float*)d_in[2];
    const float* user_tbl   = (const float*)d_in[3];
    const float* item_tbl   = (const float*)d_in[4];
    const float* entity_tbl = (const float*)d_in[5];
    const float* w_vv   = (const float*)d_in[6];
    const float* w_ev   = (const float*)d_in[7];
    const float* w_ve   = (const float*)d_in[8];
    const float* w_ee   = (const float*)d_in[9];
    const float* bias_v = (const float*)d_in[10];
    const float* bias_e = (const float*)d_in[11];
    const float* Wu = (const float*)d_in[12];
    const float* bu = (const float*)d_in[13];
    const float* W1 = (const float*)d_in[14];
    const float* b1 = (const float*)d_in[15];
    const float* W2 = (const float*)d_in[16];
    const float* b2 = (const float*)d_in[17];
    const float* W3 = (const float*)d_in[18];
    const float* b3 = (const float*)d_in[19];

    // 1) split + fragment-pack the weights into bf16 hi/lo (graph-capturable)
    convert_weights_kernel<<<(16384 + 65536 + 32768 + 255) / 256, 256>>>(Wu, W1, W2);

    // 2) fused forward
    const size_t smem = SM_FLOATS * sizeof(float);   // ~218 KB
    cudaFuncSetAttribute(multikr_kernel,
                         cudaFuncAttributeMaxDynamicSharedMemorySize, (int)smem);
    multikr_kernel<<<B_TOT / TM, NTHREADS, smem>>>(
        user_ids, item_ids, rec_target, user_tbl, item_tbl, entity_tbl,
        w_vv, w_ev, w_ve, w_ee, bias_v, bias_e,
        bu, b1, b2, W3, b3,
        (float*)d_out, out_size);
}

// round 15
// speedup vs baseline: 1.4838x; 1.0004x over previous
#include <cuda_runtime.h>
#include <cuda_bf16.h>

// MultiKR fused forward on GB300 (sm_103a), v6: bf16x3 tensor GEMMs.
//  - mma.sync.aligned.m16n8k16.row.col.f32.bf16.bf16.f32, fp32 accumulate
//  - 3-term split (ah*bh + al*bh + ah*bl): per-product error ~2^-16 -> safe
//  - K=16 per mma (vs 8 for tf32): half the mma count, half the barriers
//  - weights pre-split/pre-packed in fragment order by converter kernel
//  - activations fp32 in smem (stride 132 -> conflict-free fragment loads)
//  - cp.async double-buffered 16-row weight k-tiles (8 KB, unchanged size)
//  - cross-compress parallelized across all 512 threads
//
// Inputs (metadata order):
//  0 user_ids int32[16384]  1 item_ids int32[16384]  2 rec_target f32[16384]
//  3 user_tbl f32[100000,128] 4 item_tbl f32[50000,128] 5 entity_tbl f32[50000,128]
//  6-9 w_vv/w_ev/w_ve/w_ee f32[128]  10 bias_v 11 bias_e
// 12 Wu f32[128,128] 13 bu  14 W1 f32[256,256] 15 b1
// 16 W2 f32[256,128] 17 b2  18 W3 f32[128,1]   19 b3
// output: concat(rec_out[16384], rec_target[16384]) f32

#define B_TOT    16384
#define D        128
#define H1       256
#define H2       128
#define TM       128          // rows per CTA
#define NTHREADS 512
#define AST      132          // activation smem row stride (floats)
#define VWS      136          // vw segment stride (conflict-free 4-type access)

// dynamic smem (float offsets)
//  Us   [     0, 16896)
//  Is   [ 16896, 33792)
//  Hs   [ 33792, 50688)
//  Ws   [ 50688, 54784)   two k16 tile buffers x 2048 words (hi 1024 | lo 1024)
//  vw   [ 54784, 55328)   4 segments x VWS
//  dots [ 55328, 55840)
#define SM_FLOATS 55840

// ---- fragment-packed split bf16 weights (written by converter each launch)
// per k16 tile t: 2048 32-bit words = [hi: j(16) x lane(32) x p(2)][lo: same]
// each word = bf16x2 (even k in low half, odd k in high half)
__device__ float g_cWu[8 * 2048];             // Wu: K=128 -> 8 tiles
__device__ float g_cW1[2 * 16 * 2048];        // W1 halves: K=256 -> 16 tiles each
__device__ float g_cW2[16 * 2048];            // W2: K=256 -> 16 tiles

__global__ void convert_weights_kernel(const float* __restrict__ Wu,
                                       const float* __restrict__ W1,
                                       const float* __restrict__ W2)
{
    int i = blockIdx.x * blockDim.x + threadIdx.x;
    if (i >= 16384 + 65536 + 32768) return;
    float w; float* base; int k, n;
    if (i < 16384)      { k = i >> 7;  n = i & 127;  w = Wu[i]; base = g_cWu; }
    else if (i < 81920) { int s = i - 16384; k = s >> 8; int nf = s & 255;
                          w = W1[s]; base = g_cW1 + (nf >> 7) * (16 * 2048); n = nf & 127; }
    else                { int s = i - 81920; k = s >> 7; n = s & 127; w = W2[s]; base = g_cW2; }
    // fragment mapping for mma.m16n8k16 .col B:
    //   b0: k = 2*(lane%4)+half (k 0..7), b1: k+8; n = lane/4 within 8-col tile
    int t = k >> 4, p = (k >> 3) & 1, h = k & 1;
    int j = n >> 3, l = (n & 7) * 4 + ((k & 7) >> 1);
    int off = t * 2048 + j * 64 + l * 2 + p;          // 32-bit word index (hi block)
    __nv_bfloat16 hi = __float2bfloat16_rn(w);
    __nv_bfloat16 lo = __float2bfloat16_rn(w - __bfloat162float(hi));
    __nv_bfloat16* bp = (__nv_bfloat16*)base;
    bp[off * 2 + h]            = hi;
    bp[(off + 1024) * 2 + h]   = lo;
}

// ---- cp.async helpers ----
__device__ __forceinline__ void cp16(float* dst, const float* src) {
    unsigned s = (unsigned)__cvta_generic_to_shared(dst);
    asm volatile("cp.async.cg.shared.global [%0], [%1], 16;\n" :: "r"(s), "l"(src));
}
#define CP_COMMIT() asm volatile("cp.async.commit_group;\n" ::: "memory")
#define CP_WAIT0()  asm volatile("cp.async.wait_group 0;\n" ::: "memory")

// stage one 2048-word packed tile (512 threads x 1 cp16)
__device__ __forceinline__ void stage8(float* dst, const float* src, int tid) {
    cp16(dst + tid * 4, src + tid * 4);
}

__device__ __forceinline__ unsigned packbf(float2 v) {
    __nv_bfloat162 h = __floats2bfloat162_rn(v.x, v.y);   // .x -> low half
    return *(unsigned*)&h;
}
__device__ __forceinline__ float2 resid(float2 v, unsigned hu) {
    __nv_bfloat162 hb = *(__nv_bfloat162*)&hu;
    float2 r;
    r.x = v.x - __bfloat162float(hb.x);
    r.y = v.y - __bfloat162float(hb.y);
    return r;
}

__device__ __forceinline__ void mma16(float acc[4],
                                      unsigned a0, unsigned a1, unsigned a2, unsigned a3,
                                      unsigned b0, unsigned b1)
{
    asm("mma.sync.aligned.m16n8k16.row.col.f32.bf16.bf16.f32 "
        "{%0,%1,%2,%3},{%4,%5,%6,%7},{%8,%9},{%0,%1,%2,%3};"
        : "+f"(acc[0]), "+f"(acc[1]), "+f"(acc[2]), "+f"(acc[3])
        : "r"(a0), "r"(a1), "r"(a2), "r"(a3), "r"(b0), "r"(b1));
}

// GEMM: C[TM x 128] += A * W ; A = [A0 | A1] switching at tswitch (k16 steps).
// Warp covers 16 rows x 64 cols (8 n-tiles at jbase). 3-term bf16 split.
__device__ __forceinline__ void gemm_bf16(const float* __restrict__ A0,
                                          const float* __restrict__ A1, int tswitch,
                                          const float* __restrict__ Wsrc, int ksteps,
                                          float* Ws, int tid, int lane, int r0, int jbase,
                                          float acc[8][4], bool prefetched)
{
    if (!prefetched) { stage8(Ws, Wsrc, tid); CP_COMMIT(); }
    for (int t = 0; t < ksteps; ++t) {
        CP_WAIT0(); __syncthreads();
        if (t + 1 < ksteps) { stage8(Ws + ((t + 1) & 1) * 2048, Wsrc + (t + 1) * 2048, tid); CP_COMMIT(); }
        const float* A = (t < tswitch) ? A0 : A1;
        const int kk = (t * 16) & 127;
        const int rr = r0 + (lane >> 2);
        const int cc = kk + 2 * (lane & 3);
        float2 v00 = *(const float2*)(A + rr * AST + cc);
        float2 v01 = *(const float2*)(A + rr * AST + cc + 8);
        float2 v10 = *(const float2*)(A + (rr + 8) * AST + cc);
        float2 v11 = *(const float2*)(A + (rr + 8) * AST + cc + 8);
        unsigned ah0 = packbf(v00), ah1 = packbf(v10), ah2 = packbf(v01), ah3 = packbf(v11);
        unsigned al0 = packbf(resid(v00, ah0));
        unsigned al1 = packbf(resid(v10, ah1));
        unsigned al2 = packbf(resid(v01, ah2));
        unsigned al3 = packbf(resid(v11, ah3));
        const float* Wb = Ws + (t & 1) * 2048;
        #pragma unroll
        for (int j = 0; j < 8; ++j) {
            const int jj = jbase + j;
            float2 bh = *(const float2*)(Wb + jj * 64 + lane * 2);
            float2 bl = *(const float2*)(Wb + 1024 + jj * 64 + lane * 2);
            unsigned bh0 = __float_as_uint(bh.x), bh1 = __float_as_uint(bh.y);
            unsigned bl0 = __float_as_uint(bl.x), bl1 = __float_as_uint(bl.y);
            mma16(acc[j], ah0, ah1, ah2, ah3, bh0, bh1);
            mma16(acc[j], al0, al1, al2, al3, bh0, bh1);
            mma16(acc[j], ah0, ah1, ah2, ah3, bl0, bl1);
        }
    }
}

__device__ __forceinline__ void acc_clear(float acc[8][4]) {
    #pragma unroll
    for (int j = 0; j < 8; ++j)
        #pragma unroll
        for (int c = 0; c < 4; ++c) acc[j][c] = 0.f;
}

// relu(acc + bias) -> Dst (stride AST); warp covers cols [jbase*8, jbase*8+64)
__device__ __forceinline__ void epilogue(float acc[8][4], float* Dst,
                                         const float* bias, int lane, int r0, int jbase)
{
    const int row = r0 + (lane >> 2);
    const int cb  = 2 * (lane & 3);
    #pragma unroll
    for (int j = 0; j < 8; ++j) {
        int col = 8 * (jbase + j) + cb;
        float2 v0, v1;
        v0.x = fmaxf(acc[j][0] + bias[col],     0.f);
        v0.y = fmaxf(acc[j][1] + bias[col + 1], 0.f);
        v1.x = fmaxf(acc[j][2] + bias[col],     0.f);
        v1.y = fmaxf(acc[j][3] + bias[col + 1], 0.f);
        *(float2*)(Dst + row * AST + col)       = v0;
        *(float2*)(Dst + (row + 8) * AST + col) = v1;
    }
}

__global__ __launch_bounds__(NTHREADS, 1)
void multikr_kernel(const int*   __restrict__ user_ids,
                    const int*   __restrict__ item_ids,
                    const float* __restrict__ rec_target,
                    const float* __restrict__ user_tbl,
                    const float* __restrict__ item_tbl,
                    const float* __restrict__ entity_tbl,
                    const float* __restrict__ w_vv,
                    const float* __restrict__ w_ev,
                    const float* __restrict__ w_ve,
                    const float* __restrict__ w_ee,
                    const float* __restrict__ bias_v_p,
                    const float* __restrict__ bias_e_p,
                    const float* __restrict__ bu,
                    const float* __restrict__ b1,
                    const float* __restrict__ b2,
                    const float* __restrict__ W3,
                    const float* __restrict__ b3,
                    float* __restrict__ out,
                    int out_size)
{
    extern __shared__ float sm[];
    float* Us   = sm;
    float* Is   = sm + 16896;
    float* Hs   = sm + 33792;
    float* Ws   = sm + 50688;
    float* vw   = sm + 54784;          // 4 segments of VWS
    float* dots = sm + 55328;

    __shared__ int   s_uid[TM];
    __shared__ int   s_iid[TM];
    __shared__ float s_bu[D];
    __shared__ float s_b1[H1];
    __shared__ float s_b2[H2];
    __shared__ float s_w3[H2];

    const int tid   = threadIdx.x;
    const int lane  = tid & 31;
    const int wid   = tid >> 5;          // 0..15
    const int r0    = (wid >> 1) * 16;   // 8 row-groups of 16
    const int jbase = (wid & 1) * 8;     // n-half: tiles [jbase, jbase+8)
    const int b0    = blockIdx.x * TM;

    if (tid < TM) {
        s_uid[tid] = user_ids[b0 + tid];
        s_iid[tid] = item_ids[b0 + tid];
        vw[tid]           = w_vv[tid];   // seg 0: head . w_vv -> hv
        vw[VWS + tid]     = w_ev[tid];   // seg 1: item . w_ev -> iv
        vw[2 * VWS + tid] = w_ve[tid];   // seg 2: head . w_ve -> he
        vw[3 * VWS + tid] = w_ee[tid];   // seg 3: item . w_ee -> ie
        s_bu[tid] = bu[tid];
        s_b2[tid] = b2[tid];
        s_w3[tid] = W3[tid];
    }
    if (tid < H1) s_b1[tid] = b1[tid];

    // prefetch first Wu tile (Ws disjoint; overlaps with the gather)
    stage8(Ws, g_cWu, tid); CP_COMMIT();
    __syncthreads();

    // ---- gather embedding rows (coalesced float4, stride AST) ----
    {
        const float4* ut = (const float4*)user_tbl;
        const float4* it = (const float4*)item_tbl;
        const float4* et = (const float4*)entity_tbl;
        float4* U4 = (float4*)Us;
        float4* I4 = (float4*)Is;
        float4* H4 = (float4*)Hs;
        #pragma unroll
        for (int t = 0; t < (TM * 32) / NTHREADS; ++t) {
            int idx = tid + t * NTHREADS;
            int row = idx >> 5, q = idx & 31;
            U4[row * (AST / 4) + q] = ut[(long)s_uid[row] * 32 + q];
            I4[row * (AST / 4) + q] = it[(long)s_iid[row] * 32 + q];
            H4[row * (AST / 4) + q] = et[(long)s_iid[row] * 32 + q];
        }
    }
    __syncthreads();

    const float bias_v = bias_v_p[0];
    const float bias_e = bias_e_p[0];

    float acc[8][4];

    // =========================== layer loop ===========================
    for (int layer = 0; layer < 2; ++layer) {
        // ---- user = relu(user @ Wu + bu) ----
        acc_clear(acc);
        gemm_bf16(Us, Us, 8, g_cWu, 8, Ws, tid, lane, r0, jbase, acc, layer == 0);
        __syncthreads();                 // all reads of Us done
        epilogue(acc, Us, s_bu, lane, r0, jbase);
        __syncthreads();

        // ---- cross-compress: one dot per thread (512 = 128 rows x 4 dots) ----
        {
            const int row  = tid >> 2;
            const int type = tid & 3;
            const float* src = (type & 1) ? Is : Hs;   // 0,2: head; 1,3: item
            const float* wv  = vw + type * VWS;
            const float* sr  = src + row * AST;
            float d = 0.f;
            #pragma unroll 4
            for (int kk = 0; kk < D; ++kk) {
                int k = (kk + row) & (D - 1);          // row-skewed
                d = fmaf(sr[k], wv[k], d);
            }
            dots[type * 128 + row] = d;
        }
        __syncthreads();
        #pragma unroll
        for (int t = 0; t < (TM * D) / NTHREADS; ++t) {
            int idx = tid + t * NTHREADS;
            int row = idx >> 7, col = idx & 127;
            int a = row * AST + col;
            float i0 = Is[a], h0 = Hs[a];
            float hv = dots[row],       iv = dots[128 + row];
            float he = dots[256 + row], ie = dots[384 + row];
            Is[a] = fmaf(i0, hv, fmaf(h0, iv, bias_v));
            Hs[a] = fmaf(i0, he, fmaf(h0, ie, bias_e));
        }
        __syncthreads();
    }

    // ================= MLP =================
    // h1 half0 -> Hs (head acts dead), half1 -> Us (user acts dead after reads)
    acc_clear(acc);
    gemm_bf16(Us, Is, 8, g_cW1, 16, Ws, tid, lane, r0, jbase, acc, false);
    __syncthreads();
    epilogue(acc, Hs, s_b1, lane, r0, jbase);
    __syncthreads();

    acc_clear(acc);
    gemm_bf16(Us, Is, 8, g_cW1 + 16 * 2048, 16, Ws, tid, lane, r0, jbase, acc, false);
    __syncthreads();
    epilogue(acc, Us, s_b1 + 128, lane, r0, jbase);
    __syncthreads();

    // h2 = relu([Hs|Us] @ W2 + b2) -> Is (item acts dead)
    acc_clear(acc);
    gemm_bf16(Hs, Us, 8, g_cW2, 16, Ws, tid, lane, r0, jbase, acc, false);
    __syncthreads();
    epilogue(acc, Is, s_b2, lane, r0, jbase);
    __syncthreads();

    // out = relu(h2 @ W3 + b3)
    if (tid < TM) {
        const int row = tid;
        const float* hr = Is + row * AST;
        float d = 0.f;
        #pragma unroll 4
        for (int kk = 0; kk < D; ++kk) {
            int k = (kk + row) & (D - 1);
            d = fmaf(hr[k], s_w3[k], d);
        }
        out[b0 + row] = fmaxf(d + b3[0], 0.f);
        if (out_size >= 2 * B_TOT)
            out[B_TOT + b0 + row] = rec_target[b0 + row];
    }
}

extern "C" void kernel_launch(void* const* d_in, const int* in_sizes, int n_in,
                              void* d_out, int out_size)
{
    (void)n_in; (void)in_sizes;
    const int*   user_ids   = (const int*)  d_in[0];
    const int*   item_ids   = (const int*)  d_in[1];
    const float* rec_target = (const float*)d_in[2];
    const float* user_tbl   = (const float*)d_in[3];
    const float* item_tbl   = (const float*)d_in[4];
    const float* entity_tbl = (const float*)d_in[5];
    const float* w_vv   = (const float*)d_in[6];
    const float* w_ev   = (const float*)d_in[7];
    const float* w_ve   = (const float*)d_in[8];
    const float* w_ee   = (const float*)d_in[9];
    const float* bias_v = (const float*)d_in[10];
    const float* bias_e = (const float*)d_in[11];
    const float* Wu = (const float*)d_in[12];
    const float* bu = (const float*)d_in[13];
    const float* W1 = (const float*)d_in[14];
    const float* b1 = (const float*)d_in[15];
    const float* W2 = (const float*)d_in[16];
    const float* b2 = (const float*)d_in[17];
    const float* W3 = (const float*)d_in[18];
    const float* b3 = (const float*)d_in[19];

    // 1) split + fragment-pack the weights into bf16 hi/lo (graph-capturable)
    convert_weights_kernel<<<(16384 + 65536 + 32768 + 255) / 256, 256>>>(Wu, W1, W2);

    // 2) fused forward
    const size_t smem = SM_FLOATS * sizeof(float);   // ~218 KB
    cudaFuncSetAttribute(multikr_kernel,
                         cudaFuncAttributeMaxDynamicSharedMemorySize, (int)smem);
    multikr_kernel<<<B_TOT / TM, NTHREADS, smem>>>(
        user_ids, item_ids, rec_target, user_tbl, item_tbl, entity_tbl,
        w_vv, w_ev, w_ve, w_ee, bias_v, bias_e,
        bu, b1, b2, W3, b3,
        (float*)d_out, out_size);
}

// round 16
// speedup vs baseline: 1.7041x; 1.1484x over previous
#include <cuda_runtime.h>
#include <cuda_bf16.h>

// MultiKR fused forward on GB300 (sm_103a), v7: bf16x3 tensor GEMMs,
// 32x32 warp tiles + bf16 hi/lo plane activation storage.
//  - mma.sync.aligned.m16n8k16 bf16, fp32 accumulate, 3-term split
//  - activations stored as bf16 hi/lo planes (row: 64 hi words | 64 lo words,
//    stride 132) -> A fragments are direct conflict-free LDS.32, no pack ALU
//  - 16 warps: warp = 32 rows x 32 cols (B crossbar redundancy halved)
//  - weights pre-split/pre-packed in fragment order by converter kernel
//  - cp.async double-buffered 16-row weight k-tiles
//
// Inputs (metadata order):
//  0 user_ids int32[16384]  1 item_ids int32[16384]  2 rec_target f32[16384]
//  3 user_tbl f32[100000,128] 4 item_tbl f32[50000,128] 5 entity_tbl f32[50000,128]
//  6-9 w_vv/w_ev/w_ve/w_ee f32[128]  10 bias_v 11 bias_e
// 12 Wu f32[128,128] 13 bu  14 W1 f32[256,256] 15 b1
// 16 W2 f32[256,128] 17 b2  18 W3 f32[128,1]   19 b3
// output: concat(rec_out[16384], rec_target[16384]) f32

#define B_TOT    16384
#define D        128
#define H1       256
#define H2       128
#define TM       128
#define NTHREADS 512
#define AST      132          // words per activation row: [64 hi][2 pad][64 lo][2 pad]
#define LO_OFF   66
#define VWS      136

// dynamic smem (word offsets)
//  Us   [     0, 16896)
//  Is   [ 16896, 33792)
//  Hs   [ 33792, 50688)
//  Ws   [ 50688, 54784)   two k16 tile buffers x 2048 words (hi 1024 | lo 1024)
//  vw   [ 54784, 55328)
//  dots [ 55328, 55840)
#define SM_FLOATS 55840

// fragment-packed split bf16 weights (written by converter each launch)
__device__ float g_cWu[8 * 2048];
__device__ float g_cW1[2 * 16 * 2048];
__device__ float g_cW2[16 * 2048];

__global__ void convert_weights_kernel(const float* __restrict__ Wu,
                                       const float* __restrict__ W1,
                                       const float* __restrict__ W2)
{
    int i = blockIdx.x * blockDim.x + threadIdx.x;
    if (i >= 16384 + 65536 + 32768) return;
    float w; float* base; int k, n;
    if (i < 16384)      { k = i >> 7;  n = i & 127;  w = Wu[i]; base = g_cWu; }
    else if (i < 81920) { int s = i - 16384; k = s >> 8; int nf = s & 255;
                          w = W1[s]; base = g_cW1 + (nf >> 7) * (16 * 2048); n = nf & 127; }
    else                { int s = i - 81920; k = s >> 7; n = s & 127; w = W2[s]; base = g_cW2; }
    // mma.m16n8k16 .col B frag: b0 k=2*(lane%4)+h, b1 k+8; n = lane/4 in 8-col tile
    int t = k >> 4, p = (k >> 3) & 1, h = k & 1;
    int j = n >> 3, l = (n & 7) * 4 + ((k & 7) >> 1);
    int off = t * 2048 + j * 64 + l * 2 + p;
    __nv_bfloat16 hi = __float2bfloat16_rn(w);
    __nv_bfloat16 lo = __float2bfloat16_rn(w - __bfloat162float(hi));
    __nv_bfloat16* bp = (__nv_bfloat16*)base;
    bp[off * 2 + h]          = hi;
    bp[(off + 1024) * 2 + h] = lo;
}

// ---- helpers ----
__device__ __forceinline__ void cp16(float* dst, const float* src) {
    unsigned s = (unsigned)__cvta_generic_to_shared(dst);
    asm volatile("cp.async.cg.shared.global [%0], [%1], 16;\n" :: "r"(s), "l"(src));
}
#define CP_COMMIT() asm volatile("cp.async.commit_group;\n" ::: "memory")
#define CP_WAIT0()  asm volatile("cp.async.wait_group 0;\n" ::: "memory")

__device__ __forceinline__ void stage8(float* dst, const float* src, int tid) {
    cp16(dst + tid * 4, src + tid * 4);
}

__device__ __forceinline__ unsigned packbf2(float x, float y) {
    __nv_bfloat162 h = __floats2bfloat162_rn(x, y);    // x -> low half
    return *(unsigned*)&h;
}
__device__ __forceinline__ float2 unpackbf(unsigned u) {
    __nv_bfloat162 h = *(__nv_bfloat162*)&u;
    return __bfloat1622float2(h);
}
// store fp32 pair (x,y) as hi word + lo word
__device__ __forceinline__ void store_pair(unsigned* row, int word, float x, float y) {
    unsigned hw = packbf2(x, y);
    float2 hv = unpackbf(hw);
    unsigned lw = packbf2(x - hv.x, y - hv.y);
    row[word]          = hw;
    row[word + LO_OFF] = lw;
}
// reconstruct fp32 pair from planes
__device__ __forceinline__ float2 load_pair(const unsigned* row, int word) {
    float2 h = unpackbf(row[word]);
    float2 l = unpackbf(row[word + LO_OFF]);
    h.x += l.x; h.y += l.y;
    return h;
}

__device__ __forceinline__ void mma16(float acc[4],
                                      unsigned a0, unsigned a1, unsigned a2, unsigned a3,
                                      unsigned b0, unsigned b1)
{
    asm("mma.sync.aligned.m16n8k16.row.col.f32.bf16.bf16.f32 "
        "{%0,%1,%2,%3},{%4,%5,%6,%7},{%8,%9},{%0,%1,%2,%3};"
        : "+f"(acc[0]), "+f"(acc[1]), "+f"(acc[2]), "+f"(acc[3])
        : "r"(a0), "r"(a1), "r"(a2), "r"(a3), "r"(b0), "r"(b1));
}

// GEMM: C[TM x 128] += A * W ; A = [A0|A1] switching at tswitch (k16 steps).
// Warp = 32 rows (base r0) x 32 cols (j tiles jg*4..jg*4+3). acc[j*2+m][4].
__device__ __forceinline__ void gemm_bf16(const float* __restrict__ A0,
                                          const float* __restrict__ A1, int tswitch,
                                          const float* __restrict__ Wsrc, int ksteps,
                                          float* Ws, int tid, int lane, int r0, int jg,
                                          float acc[8][4], bool prefetched)
{
    if (!prefetched) { stage8(Ws, Wsrc, tid); CP_COMMIT(); }
    for (int t = 0; t < ksteps; ++t) {
        CP_WAIT0(); __syncthreads();
        if (t + 1 < ksteps) { stage8(Ws + ((t + 1) & 1) * 2048, Wsrc + (t + 1) * 2048, tid); CP_COMMIT(); }
        const unsigned* Ap = (const unsigned*)((t < tswitch) ? A0 : A1);
        const int wq = (((t * 16) & 127) >> 1) + (lane & 3);
        unsigned ah[2][4], al[2][4];
        #pragma unroll
        for (int m = 0; m < 2; ++m) {
            int base = (r0 + m * 16 + (lane >> 2)) * AST + wq;
            ah[m][0] = Ap[base];            ah[m][2] = Ap[base + 4];
            ah[m][1] = Ap[base + 8 * AST];  ah[m][3] = Ap[base + 8 * AST + 4];
            al[m][0] = Ap[base + LO_OFF];           al[m][2] = Ap[base + LO_OFF + 4];
            al[m][1] = Ap[base + 8 * AST + LO_OFF]; al[m][3] = Ap[base + 8 * AST + LO_OFF + 4];
        }
        const float* Wb = Ws + (t & 1) * 2048;
        #pragma unroll
        for (int j = 0; j < 4; ++j) {
            const int jj = jg * 4 + j;
            float2 bh = *(const float2*)(Wb + jj * 64 + lane * 2);
            float2 bl = *(const float2*)(Wb + 1024 + jj * 64 + lane * 2);
            unsigned bh0 = __float_as_uint(bh.x), bh1 = __float_as_uint(bh.y);
            unsigned bl0 = __float_as_uint(bl.x), bl1 = __float_as_uint(bl.y);
            #pragma unroll
            for (int m = 0; m < 2; ++m) {
                mma16(acc[j * 2 + m], ah[m][0], ah[m][1], ah[m][2], ah[m][3], bh0, bh1);
                mma16(acc[j * 2 + m], al[m][0], al[m][1], al[m][2], al[m][3], bh0, bh1);
                mma16(acc[j * 2 + m], ah[m][0], ah[m][1], ah[m][2], ah[m][3], bl0, bl1);
            }
        }
    }
}

__device__ __forceinline__ void acc_clear(float acc[8][4]) {
    #pragma unroll
    for (int j = 0; j < 8; ++j)
        #pragma unroll
        for (int c = 0; c < 4; ++c) acc[j][c] = 0.f;
}

// relu(acc + bias) -> Dst planes. Warp = rows [r0,r0+32), cols [jg*32, jg*32+32)
__device__ __forceinline__ void epilogue(float acc[8][4], float* Dst,
                                         const float* bias, int lane, int r0, int jg)
{
    unsigned* Dp = (unsigned*)Dst;
    const int g  = lane >> 2;
    const int q  = lane & 3;
    #pragma unroll
    for (int m = 0; m < 2; ++m) {
        int row = r0 + m * 16 + g;
        unsigned* rp0 = Dp + row * AST;
        unsigned* rp1 = Dp + (row + 8) * AST;
        #pragma unroll
        for (int j = 0; j < 4; ++j) {
            int jj  = jg * 4 + j;
            int col = 8 * jj + 2 * q;
            int wrd = 4 * jj + q;
            float* c = acc[j * 2 + m];
            store_pair(rp0, wrd, fmaxf(c[0] + bias[col], 0.f), fmaxf(c[1] + bias[col + 1], 0.f));
            store_pair(rp1, wrd, fmaxf(c[2] + bias[col], 0.f), fmaxf(c[3] + bias[col + 1], 0.f));
        }
    }
}

__global__ __launch_bounds__(NTHREADS, 1)
void multikr_kernel(const int*   __restrict__ user_ids,
                    const int*   __restrict__ item_ids,
                    const float* __restrict__ rec_target,
                    const float* __restrict__ user_tbl,
                    const float* __restrict__ item_tbl,
                    const float* __restrict__ entity_tbl,
                    const float* __restrict__ w_vv,
                    const float* __restrict__ w_ev,
                    const float* __restrict__ w_ve,
                    const float* __restrict__ w_ee,
                    const float* __restrict__ bias_v_p,
                    const float* __restrict__ bias_e_p,
                    const float* __restrict__ bu,
                    const float* __restrict__ b1,
                    const float* __restrict__ b2,
                    const float* __restrict__ W3,
                    const float* __restrict__ b3,
                    float* __restrict__ out,
                    int out_size)
{
    extern __shared__ float sm[];
    float* Us   = sm;
    float* Is   = sm + 16896;
    float* Hs   = sm + 33792;
    float* Ws   = sm + 50688;
    float* vw   = sm + 54784;
    float* dots = sm + 55328;

    __shared__ int   s_uid[TM];
    __shared__ int   s_iid[TM];
    __shared__ float s_bu[D];
    __shared__ float s_b1[H1];
    __shared__ float s_b2[H2];
    __shared__ float s_w3[H2];

    const int tid  = threadIdx.x;
    const int lane = tid & 31;
    const int wid  = tid >> 5;
    const int r0   = (wid >> 2) * 32;    // 4 row-groups of 32
    const int jg   = wid & 3;            // 4 col-groups of 32
    const int b0   = blockIdx.x * TM;

    if (tid < TM) {
        s_uid[tid] = user_ids[b0 + tid];
        s_iid[tid] = item_ids[b0 + tid];
        vw[tid]           = w_vv[tid];
        vw[VWS + tid]     = w_ev[tid];
        vw[2 * VWS + tid] = w_ve[tid];
        vw[3 * VWS + tid] = w_ee[tid];
        s_bu[tid] = bu[tid];
        s_b2[tid] = b2[tid];
        s_w3[tid] = W3[tid];
    }
    if (tid < H1) s_b1[tid] = b1[tid];

    // prefetch first Wu tile (overlaps with gather)
    stage8(Ws, g_cWu, tid); CP_COMMIT();
    __syncthreads();

    // ---- gather embedding rows -> bf16 hi/lo planes ----
    {
        const float4* ut = (const float4*)user_tbl;
        const float4* it = (const float4*)item_tbl;
        const float4* et = (const float4*)entity_tbl;
        unsigned* Up = (unsigned*)Us;
        unsigned* Ip = (unsigned*)Is;
        unsigned* Hp = (unsigned*)Hs;
        #pragma unroll
        for (int t = 0; t < (TM * 32) / NTHREADS; ++t) {
            int idx = tid + t * NTHREADS;
            int row = idx >> 5, q = idx & 31;
            float4 u = ut[(long)s_uid[row] * 32 + q];
            float4 i = it[(long)s_iid[row] * 32 + q];
            float4 h = et[(long)s_iid[row] * 32 + q];
            store_pair(Up + row * AST, 2 * q,     u.x, u.y);
            store_pair(Up + row * AST, 2 * q + 1, u.z, u.w);
            store_pair(Ip + row * AST, 2 * q,     i.x, i.y);
            store_pair(Ip + row * AST, 2 * q + 1, i.z, i.w);
            store_pair(Hp + row * AST, 2 * q,     h.x, h.y);
            store_pair(Hp + row * AST, 2 * q + 1, h.z, h.w);
        }
    }
    __syncthreads();

    const float bias_v = bias_v_p[0];
    const float bias_e = bias_e_p[0];

    float acc[8][4];

    // =========================== layer loop ===========================
    for (int layer = 0; layer < 2; ++layer) {
        // ---- user = relu(user @ Wu + bu) ----
        acc_clear(acc);
        gemm_bf16(Us, Us, 8, g_cWu, 8, Ws, tid, lane, r0, jg, acc, layer == 0);
        __syncthreads();
        epilogue(acc, Us, s_bu, lane, r0, jg);
        __syncthreads();

        // ---- cross-compress dots: one per thread (128 rows x 4 types) ----
        {
            const int row  = tid >> 2;
            const int type = tid & 3;
            const unsigned* sp = (const unsigned*)((type & 1) ? Is : Hs) + row * AST;
            const float* wv = vw + type * VWS;
            float d = 0.f;
            #pragma unroll 4
            for (int pp = 0; pp < 64; ++pp) {
                int p = (pp + row) & 63;               // row-skewed
                float2 f = load_pair(sp, p);
                d = fmaf(f.x, wv[2 * p],     d);
                d = fmaf(f.y, wv[2 * p + 1], d);
            }
            dots[type * 128 + row] = d;
        }
        __syncthreads();
        // ---- cross-compress update (pairwise) ----
        {
            unsigned* Ip = (unsigned*)Is;
            unsigned* Hp = (unsigned*)Hs;
            #pragma unroll
            for (int t = 0; t < (TM * 64) / NTHREADS; ++t) {
                int pid = tid + t * NTHREADS;
                int row = pid >> 6, p = pid & 63;
                unsigned* ir = Ip + row * AST;
                unsigned* hr = Hp + row * AST;
                float2 iv2 = load_pair(ir, p);
                float2 hv2 = load_pair(hr, p);
                float hv = dots[row],       iv = dots[128 + row];
                float he = dots[256 + row], ie = dots[384 + row];
                float nix = fmaf(iv2.x, hv, fmaf(hv2.x, iv, bias_v));
                float niy = fmaf(iv2.y, hv, fmaf(hv2.y, iv, bias_v));
                float nhx = fmaf(iv2.x, he, fmaf(hv2.x, ie, bias_e));
                float nhy = fmaf(iv2.y, he, fmaf(hv2.y, ie, bias_e));
                store_pair(ir, p, nix, niy);
                store_pair(hr, p, nhx, nhy);
            }
        }
        __syncthreads();
    }

    // ================= MLP =================
    // h1 half0 -> Hs (head dead), half1 -> Us (user dead after reads)
    acc_clear(acc);
    gemm_bf16(Us, Is, 8, g_cW1, 16, Ws, tid, lane, r0, jg, acc, false);
    __syncthreads();
    epilogue(acc, Hs, s_b1, lane, r0, jg);
    __syncthreads();

    acc_clear(acc);
    gemm_bf16(Us, Is, 8, g_cW1 + 16 * 2048, 16, Ws, tid, lane, r0, jg, acc, false);
    __syncthreads();
    epilogue(acc, Us, s_b1 + 128, lane, r0, jg);
    __syncthreads();

    // h2 = relu([Hs|Us] @ W2 + b2) -> Is (item dead)
    acc_clear(acc);
    gemm_bf16(Hs, Us, 8, g_cW2, 16, Ws, tid, lane, r0, jg, acc, false);
    __syncthreads();
    epilogue(acc, Is, s_b2, lane, r0, jg);
    __syncthreads();

    // out = relu(h2 @ W3 + b3)
    if (tid < TM) {
        const int row = tid;
        const unsigned* hr = (const unsigned*)Is + row * AST;
        float d = 0.f;
        #pragma unroll 4
        for (int pp = 0; pp < 64; ++pp) {
            int p = (pp + row) & 63;
            float2 f = load_pair(hr, p);
            d = fmaf(f.x, s_w3[2 * p],     d);
            d = fmaf(f.y, s_w3[2 * p + 1], d);
        }
        out[b0 + row] = fmaxf(d + b3[0], 0.f);
        if (out_size >= 2 * B_TOT)
            out[B_TOT + b0 + row] = rec_target[b0 + row];
    }
}

extern "C" void kernel_launch(void* const* d_in, const int* in_sizes, int n_in,
                              void* d_out, int out_size)
{
    (void)n_in; (void)in_sizes;
    const int*   user_ids   = (const int*)  d_in[0];
    const int*   item_ids   = (const int*)  d_in[1];
    const float* rec_target = (const float*)d_in[2];
    const float* user_tbl   = (const float*)d_in[3];
    const float* item_tbl   = (const float*)d_in[4];
    const float* entity_tbl = (const float*)d_in[5];
    const float* w_vv   = (const float*)d_in[6];
    const float* w_ev   = (const float*)d_in[7];
    const float* w_ve   = (const float*)d_in[8];
    const float* w_ee   = (const float*)d_in[9];
    const float* bias_v = (const float*)d_in[10];
    const float* bias_e = (const float*)d_in[11];
    const float* Wu = (const float*)d_in[12];
    const float* bu = (const float*)d_in[13];
    const float* W1 = (const float*)d_in[14];
    const float* b1 = (const float*)d_in[15];
    const float* W2 = (const float*)d_in[16];
    const float* b2 = (const float*)d_in[17];
    const float* W3 = (const float*)d_in[18];
    const float* b3 = (const float*)d_in[19];

    convert_weights_kernel<<<(16384 + 65536 + 32768 + 255) / 256, 256>>>(Wu, W1, W2);

    const size_t smem = SM_FLOATS * sizeof(float);   // ~223 KB
    cudaFuncSetAttribute(multikr_kernel,
                         cudaFuncAttributeMaxDynamicSharedMemorySize, (int)smem);
    multikr_kernel<<<B_TOT / TM, NTHREADS, smem>>>(
        user_ids, item_ids, rec_target, user_tbl, item_tbl, entity_tbl,
        w_vv, w_ev, w_ve, w_ee, bias_v, bias_e,
        bu, b1, b2, W3, b3,
        (float*)d_out, out_size);
}